// round 7
// baseline (speedup 1.0000x reference)
#include <cuda_runtime.h>
#include <cuda_bf16.h>
#include <cstdint>

// LSTM_WP via mma.sync bf16 m16n8k16. Cluster of 2 CTAs; CTA rank c owns
// gate-rows for units c*64..c*64+63 (all 4 gates, M=256), W in registers.
// R6: batch tile split into TWO independent N=32 tiles (A: n 0-31, B: n 32-63)
// with separate double-buffered h and separate cluster mbarriers, software-
// pipelined per warp: wait(A),MMA(A),wait(B),MMA(B),epi(A),epi(B). MUFU
// epilogue of A overlaps tensor-pipe drain of B; barrier latency hidden.

#define TT 128
#define NTHR 256
#define OFF_HA  0                        // 2 x 8192 B bf16 h (tile A)
#define OFF_HB  16384                    // 2 x 8192 B bf16 h (tile B)
#define OFF_X   32768                    // 64 x 129 x 4 = 33024 B padded x
#define OFF_HF  65792                    // 64 x 129 x 4 fp32 final h
#define OFF_BAR 98816
#define SMEM_REQ (OFF_BAR + 64)

__device__ __forceinline__ uint32_t smem_u32(const void* p) {
    uint32_t a;
    asm("{ .reg .u64 t; cvta.to.shared.u64 t, %1; cvt.u32.u64 %0, t; }" : "=r"(a) : "l"(p));
    return a;
}
__device__ __forceinline__ uint32_t ctarank() {
    uint32_t r; asm("mov.u32 %0, %%cluster_ctarank;" : "=r"(r)); return r;
}
__device__ __forceinline__ uint32_t pk_bf16(float lo, float hi) {
    uint32_t r; asm("cvt.rn.bf16x2.f32 %0, %1, %2;" : "=r"(r) : "f"(hi), "f"(lo)); return r;
}
__device__ __forceinline__ float tanh_ap(float x) {
    float y; asm("tanh.approx.f32 %0, %1;" : "=f"(y) : "f"(x)); return y;
}
__device__ __forceinline__ float sig_ap(float x) { return fmaf(tanh_ap(0.5f * x), 0.5f, 0.5f); }

#define MBAR_INIT(a, n) \
    asm volatile("mbarrier.init.shared.b64 [%0], %1;" :: "r"(a), "r"((uint32_t)(n)) : "memory")

#define ARRIVE_BOTH(addr, peer) do { \
    asm volatile("mbarrier.arrive.release.cluster.shared::cta.b64 _, [%0];" \
                 :: "r"(addr) : "memory"); \
    asm volatile("{ .reg .b32 ra; mapa.shared::cluster.u32 ra, %0, %1;" \
                 " mbarrier.arrive.release.cluster.shared::cluster.b64 _, [ra]; }" \
                 :: "r"(addr), "r"((uint32_t)(peer)) : "memory"); \
} while (0)

__device__ __forceinline__ void mbar_wait(uint32_t a, uint32_t par) {
    uint32_t done;
    do {
        asm volatile("{ .reg .pred p;"
                     " mbarrier.try_wait.parity.acquire.cluster.shared::cta.b64 p, [%1], %2, 0x989680;"
                     " selp.b32 %0,1,0,p; }"
                     : "=r"(done) : "r"(a), "r"(par) : "memory");
    } while (!done);
}

#define CLUSTER_SYNC() do { \
    asm volatile("barrier.cluster.arrive.aligned;" ::: "memory"); \
    asm volatile("barrier.cluster.wait.aligned;"   ::: "memory"); } while (0)

#define MMA_BF16(d, a, b0, b1) \
    asm volatile("mma.sync.aligned.m16n8k16.row.col.f32.bf16.bf16.f32 " \
                 "{%0,%1,%2,%3}, {%4,%5,%6,%7}, {%8,%9}, {%0,%1,%2,%3};" \
                 : "+f"((d)[0]), "+f"((d)[1]), "+f"((d)[2]), "+f"((d)[3]) \
                 : "r"((a)[0]), "r"((a)[1]), "r"((a)[2]), "r"((a)[3]), \
                   "r"(b0), "r"(b1))

__global__ __launch_bounds__(NTHR, 1) __cluster_dims__(2, 1, 1)
void lstm_mma(const float* __restrict__ x,
              const float* __restrict__ W_ih,
              const float* __restrict__ W_hh,
              const float* __restrict__ b_ih,
              const float* __restrict__ b_hh,
              const float* __restrict__ fc_W,
              const float* __restrict__ fc_b,
              float* __restrict__ out)
{
    extern __shared__ char sm[];
    const uint32_t sbase = smem_u32(sm);
    const int tid  = threadIdx.x;
    const int wid  = tid >> 5, lane = tid & 31;
    const int gid  = lane >> 2, tig = lane & 3;
    const uint32_t crank = ctarank();
    const uint32_t peer  = crank ^ 1u;
    const int clid = blockIdx.x >> 1;

    // barriers: [tile A: buf0, buf1][tile B: buf0, buf1]
    const uint32_t barA0 = sbase + OFF_BAR;
    const uint32_t barA1 = sbase + OFF_BAR + 8;
    const uint32_t barB0 = sbase + OFF_BAR + 16;
    const uint32_t barB1 = sbase + OFF_BAR + 24;

    if (tid == 0) {
        MBAR_INIT(barA0, 16); MBAR_INIT(barA1, 16);
        MBAR_INIT(barB0, 16); MBAR_INIT(barB1, 16);
    }

    // zero h buf0 of both tiles, load x into padded x_s[64][129]
    {
        float4 z = make_float4(0.f, 0.f, 0.f, 0.f);
        float4* hzA = (float4*)(sm + OFF_HA);
        float4* hzB = (float4*)(sm + OFF_HB);
        #pragma unroll
        for (int i = tid; i < 512; i += NTHR) { hzA[i] = z; hzB[i] = z; }
        const float4* xg = (const float4*)(x + (size_t)clid * 64 * TT);
        float* xs = (float*)(sm + OFF_X);
        #pragma unroll
        for (int i = tid; i < 2048; i += NTHR) {
            float4 v = xg[i];
            int n = i >> 5, q = (i & 31) * 4;
            float* d = xs + n * 129 + q;
            d[0] = v.x; d[1] = v.y; d[2] = v.z; d[3] = v.w;
        }
    }
    __syncthreads();
    CLUSTER_SYNC();   // peer mbars + smem ready

    // ---- W fragments in registers (bf16x2, 64 regs) ----
    const int u = (int)crank * 64 + wid * 8 + gid;   // hidden unit 0..127
    uint32_t wreg[2][8][4];
    #pragma unroll
    for (int mt = 0; mt < 2; mt++) {
        const float* rl = W_hh + (size_t)((2 * mt)     * 128 + u) * 128;
        const float* rh = W_hh + (size_t)((2 * mt + 1) * 128 + u) * 128;
        #pragma unroll
        for (int kt = 0; kt < 8; kt++) {
            int k0 = kt * 16 + tig * 2;
            wreg[mt][kt][0] = pk_bf16(__ldg(rl + k0),     __ldg(rl + k0 + 1));
            wreg[mt][kt][1] = pk_bf16(__ldg(rh + k0),     __ldg(rh + k0 + 1));
            wreg[mt][kt][2] = pk_bf16(__ldg(rl + k0 + 8), __ldg(rl + k0 + 9));
            wreg[mt][kt][3] = pk_bf16(__ldg(rh + k0 + 8), __ldg(rh + k0 + 9));
        }
    }
    float wi[4], bsv[4];
    #pragma unroll
    for (int g = 0; g < 4; g++) {
        int row = g * 128 + u;
        wi[g] = W_ih[row]; bsv[g] = b_ih[row] + b_hh[row];
    }

    uint32_t peerbase;
    asm("mapa.shared::cluster.u32 %0, %1, %2;" : "=r"(peerbase) : "r"(sbase), "r"(peer));

    // per-thread B-frag read bases; per-unit-pair write offset
    const uint32_t bfragA = sbase + OFF_HA + (uint32_t)(gid * 32 + tig * 8);
    const uint32_t bfragB = sbase + OFF_HB + (uint32_t)(gid * 32 + tig * 8);
    const int upair = u & ~1;
    const uint32_t wordoff = (uint32_t)((upair >> 4) * 1024 + ((upair >> 1) & 3) * 8
                                        + ((upair >> 3) & 1) * 4);
    const bool even = ((gid & 1) == 0);
    const float* xs = (const float*)(sm + OFF_X);

    float cstA[8], cstB[8];
    #pragma unroll
    for (int i = 0; i < 8; i++) { cstA[i] = 0.f; cstB[i] = 0.f; }

    __syncwarp();
    if (lane == 0) { ARRIVE_BOTH(barA0, peer); ARRIVE_BOTH(barB0, peer); }

    for (int t = 0; t < TT; t++) {
        const uint32_t par = (uint32_t)((t >> 1) & 1);
        const uint32_t rbo = (uint32_t)(t & 1) * 8192;        // read buf offset
        const uint32_t wbo = (uint32_t)((t + 1) & 1) * 8192;  // write buf offset

        float accA[2][4][4], accB[2][4][4];
        #pragma unroll
        for (int mt = 0; mt < 2; mt++)
            #pragma unroll
            for (int nt = 0; nt < 4; nt++)
                #pragma unroll
                for (int r = 0; r < 4; r++) { accA[mt][nt][r] = 0.f; accB[mt][nt][r] = 0.f; }

        // ---- tile A: wait + MMA ----
        mbar_wait((t & 1) ? barA1 : barA0, par);
        #pragma unroll
        for (int kt = 0; kt < 8; kt++) {
            uint32_t b0[4], b1[4];
            #pragma unroll
            for (int nt = 0; nt < 4; nt++)
                asm volatile("ld.shared.v2.b32 {%0,%1}, [%2];"
                             : "=r"(b0[nt]), "=r"(b1[nt])
                             : "r"(bfragA + rbo + (uint32_t)(kt * 1024 + nt * 256)));
            #pragma unroll
            for (int mt = 0; mt < 2; mt++)
                #pragma unroll
                for (int nt = 0; nt < 4; nt++)
                    MMA_BF16(accA[mt][nt], wreg[mt][kt], b0[nt], b1[nt]);
        }

        // ---- tile B: wait + MMA (overlaps A's tensor drain) ----
        mbar_wait((t & 1) ? barB1 : barB0, par);
        #pragma unroll
        for (int kt = 0; kt < 8; kt++) {
            uint32_t b0[4], b1[4];
            #pragma unroll
            for (int nt = 0; nt < 4; nt++)
                asm volatile("ld.shared.v2.b32 {%0,%1}, [%2];"
                             : "=r"(b0[nt]), "=r"(b1[nt])
                             : "r"(bfragB + rbo + (uint32_t)(kt * 1024 + nt * 256)));
            #pragma unroll
            for (int mt = 0; mt < 2; mt++)
                #pragma unroll
                for (int nt = 0; nt < 4; nt++)
                    MMA_BF16(accB[mt][nt], wreg[mt][kt], b0[nt], b1[nt]);
        }

        // ---- epilogue A (MUFU overlaps B's tensor work) ----
        {
            const uint32_t wL = sbase    + OFF_HA + wbo + wordoff;
            const uint32_t wR = peerbase + OFF_HA + wbo + wordoff;
            #pragma unroll
            for (int nt = 0; nt < 4; nt++) {
                #pragma unroll
                for (int e = 0; e < 2; e++) {
                    const int n = nt * 8 + tig * 2 + e;          // 0..31
                    const float xv = xs[n * 129 + t];
                    const float pi = accA[0][nt][e]     + fmaf(xv, wi[0], bsv[0]);
                    const float pf = accA[0][nt][2 + e] + fmaf(xv, wi[1], bsv[1]);
                    const float pg = accA[1][nt][e]     + fmaf(xv, wi[2], bsv[2]);
                    const float po = accA[1][nt][2 + e] + fmaf(xv, wi[3], bsv[3]);
                    const float gi = sig_ap(pi), gf = sig_ap(pf);
                    const float gg = tanh_ap(pg), go = sig_ap(po);
                    const float cn = fmaf(gf, cstA[nt * 2 + e], gi * gg);
                    cstA[nt * 2 + e] = cn;
                    const float hv = go * tanh_ap(cn);
                    const float hp = __shfl_xor_sync(0xffffffffu, hv, 4);
                    if (even) {
                        const uint32_t w = pk_bf16(hv, hp);
                        asm volatile("st.shared.b32 [%0], %1;"
                                     :: "r"(wL + (uint32_t)n * 32), "r"(w) : "memory");
                        asm volatile("st.shared::cluster.b32 [%0], %1;"
                                     :: "r"(wR + (uint32_t)n * 32), "r"(w) : "memory");
                        if (t == TT - 1) {
                            const uint32_t fo = (uint32_t)(OFF_HF + n * 516 + upair * 4);
                            asm volatile("st.shared.f32 [%0], %1;" :: "r"(sbase + fo), "f"(hv) : "memory");
                            asm volatile("st.shared.f32 [%0], %1;" :: "r"(sbase + fo + 4), "f"(hp) : "memory");
                            asm volatile("st.shared::cluster.f32 [%0], %1;" :: "r"(peerbase + fo), "f"(hv) : "memory");
                            asm volatile("st.shared::cluster.f32 [%0], %1;" :: "r"(peerbase + fo + 4), "f"(hp) : "memory");
                        }
                    }
                }
            }
            __syncwarp();
            if (lane == 0) ARRIVE_BOTH((t & 1) ? barA0 : barA1, peer);
        }

        // ---- epilogue B ----
        {
            const uint32_t wL = sbase    + OFF_HB + wbo + wordoff;
            const uint32_t wR = peerbase + OFF_HB + wbo + wordoff;
            #pragma unroll
            for (int nt = 0; nt < 4; nt++) {
                #pragma unroll
                for (int e = 0; e < 2; e++) {
                    const int n = nt * 8 + tig * 2 + e;          // local 0..31
                    const int ng = 32 + n;                       // global batch
                    const float xv = xs[ng * 129 + t];
                    const float pi = accB[0][nt][e]     + fmaf(xv, wi[0], bsv[0]);
                    const float pf = accB[0][nt][2 + e] + fmaf(xv, wi[1], bsv[1]);
                    const float pg = accB[1][nt][e]     + fmaf(xv, wi[2], bsv[2]);
                    const float po = accB[1][nt][2 + e] + fmaf(xv, wi[3], bsv[3]);
                    const float gi = sig_ap(pi), gf = sig_ap(pf);
                    const float gg = tanh_ap(pg), go = sig_ap(po);
                    const float cn = fmaf(gf, cstB[nt * 2 + e], gi * gg);
                    cstB[nt * 2 + e] = cn;
                    const float hv = go * tanh_ap(cn);
                    const float hp = __shfl_xor_sync(0xffffffffu, hv, 4);
                    if (even) {
                        const uint32_t w = pk_bf16(hv, hp);
                        asm volatile("st.shared.b32 [%0], %1;"
                                     :: "r"(wL + (uint32_t)n * 32), "r"(w) : "memory");
                        asm volatile("st.shared::cluster.b32 [%0], %1;"
                                     :: "r"(wR + (uint32_t)n * 32), "r"(w) : "memory");
                        if (t == TT - 1) {
                            const uint32_t fo = (uint32_t)(OFF_HF + ng * 516 + upair * 4);
                            asm volatile("st.shared.f32 [%0], %1;" :: "r"(sbase + fo), "f"(hv) : "memory");
                            asm volatile("st.shared.f32 [%0], %1;" :: "r"(sbase + fo + 4), "f"(hp) : "memory");
                            asm volatile("st.shared::cluster.f32 [%0], %1;" :: "r"(peerbase + fo), "f"(hv) : "memory");
                            asm volatile("st.shared::cluster.f32 [%0], %1;" :: "r"(peerbase + fo + 4), "f"(hp) : "memory");
                        }
                    }
                }
            }
            __syncwarp();
            if (lane == 0) ARRIVE_BOTH((t & 1) ? barB0 : barB1, peer);
        }
    }

    CLUSTER_SYNC();   // all final fp32 h writes (incl. peer stores) visible

    // ---- fc head on exact fp32 h ----
    if (wid < 2) {
        const int n = (int)crank * 32 + wid * 32 + lane;   // hmm: 2 warps x 32
        // each CTA outputs 32 batches: crank selects half; use warp 0 only
    }
    if (wid == 0) {
        const int n = (int)crank * 32 + lane;
        const float* hf = (const float*)(sm + OFF_HF) + n * 129;
        float s = 0.f;
        #pragma unroll 8
        for (int k = 0; k < 128; k++) s = fmaf(hf[k], fc_W[k], s);
        out[clid * 64 + n] = s + fc_b[0];
    }
    CLUSTER_SYNC();
}

extern "C" void kernel_launch(void* const* d_in, const int* in_sizes, int n_in,
                              void* d_out, int out_size)
{
    const float* x    = (const float*)d_in[0];
    const float* W_ih = (const float*)d_in[1];
    const float* W_hh = (const float*)d_in[2];
    const float* b_ih = (const float*)d_in[3];
    const float* b_hh = (const float*)d_in[4];
    const float* fc_W = (const float*)d_in[5];
    const float* fc_b = (const float*)d_in[6];

    const int B = in_sizes[0] / TT;        // 4096
    const int grid = (B / 64) * 2;         // 64 clusters x 2 CTAs = 128

    cudaFuncSetAttribute(lstm_mma, cudaFuncAttributeMaxDynamicSharedMemorySize, SMEM_REQ);
    lstm_mma<<<grid, NTHR, SMEM_REQ>>>(x, W_ih, W_hh, b_ih, b_hh, fc_W, fc_b, (float*)d_out);
}

// round 8
// speedup vs baseline: 1.0548x; 1.0548x over previous
#include <cuda_runtime.h>
#include <cuda_bf16.h>
#include <cstdint>

// LSTM_WP via mma.sync bf16 m16n8k16 — single-CTA edition (no cluster).
// CTA = 512 threads (16 warps), owns N=32 batches and ALL 512 gate rows:
// warp w holds rows for units u = w*8 + gid (4 gates each) in REGISTERS
// (64 bf16x2 frags). Per step: D[512,32] = W[512,128] @ h[128,32] via
// 64 m16n8k16 MMAs/warp; h bf16 double-buffered in smem; ONE __syncthreads
// per step (no DSMEM, no mbarriers). fc head from final bf16 h.

#define TT 128
#define NTHR 512

__device__ __forceinline__ uint32_t smem_u32(const void* p) {
    uint32_t a;
    asm("{ .reg .u64 t; cvta.to.shared.u64 t, %1; cvt.u32.u64 %0, t; }" : "=r"(a) : "l"(p));
    return a;
}
__device__ __forceinline__ uint32_t pk_bf16(float lo, float hi) {
    uint32_t r; asm("cvt.rn.bf16x2.f32 %0, %1, %2;" : "=r"(r) : "f"(hi), "f"(lo)); return r;
}
__device__ __forceinline__ float tanh_ap(float x) {
    float y; asm("tanh.approx.f32 %0, %1;" : "=f"(y) : "f"(x)); return y;
}
__device__ __forceinline__ float sig_ap(float x) { return fmaf(tanh_ap(0.5f * x), 0.5f, 0.5f); }

#define MMA_BF16(d, a, b0, b1) \
    asm volatile("mma.sync.aligned.m16n8k16.row.col.f32.bf16.bf16.f32 " \
                 "{%0,%1,%2,%3}, {%4,%5,%6,%7}, {%8,%9}, {%0,%1,%2,%3};" \
                 : "+f"((d)[0]), "+f"((d)[1]), "+f"((d)[2]), "+f"((d)[3]) \
                 : "r"((a)[0]), "r"((a)[1]), "r"((a)[2]), "r"((a)[3]), \
                   "r"(b0), "r"(b1))

__global__ __launch_bounds__(NTHR, 1)
void lstm_mma(const float* __restrict__ x,
              const float* __restrict__ W_ih,
              const float* __restrict__ W_hh,
              const float* __restrict__ b_ih,
              const float* __restrict__ b_hh,
              const float* __restrict__ fc_W,
              const float* __restrict__ fc_b,
              float* __restrict__ out)
{
    // h: 2 buffers x 8192 B; word[kt][n][pair-interleave] (layout from R5/R6)
    __shared__ uint32_t h_s[2][2048];
    __shared__ __nv_bfloat16 x_s[TT * 32];     // [t][n]
    __shared__ float wibs[128][8];             // per-unit: wi[4], bias[4]

    const int tid  = threadIdx.x;
    const int wid  = tid >> 5, lane = tid & 31;
    const int gid  = lane >> 2, tig = lane & 3;
    const int b0g  = blockIdx.x * 32;          // batch base
    const uint32_t hbase = smem_u32(h_s);

    // ---- stage x as bf16 [t][n]; zero h buf0 ----
    for (int i = tid; i < TT * 32; i += NTHR) {
        int n = i >> 7, t = i & 127;
        x_s[t * 32 + n] = __float2bfloat16(x[(size_t)(b0g + n) * TT + t]);
    }
    for (int i = tid; i < 2048; i += NTHR) h_s[0][i] = 0u;

    const int u = wid * 8 + gid;               // hidden unit 0..127
    if (tig == 0) {
        #pragma unroll
        for (int g = 0; g < 4; g++) {
            int row = g * 128 + u;
            wibs[u][g]     = W_ih[row];
            wibs[u][4 + g] = b_ih[row] + b_hh[row];
        }
    }

    // ---- W fragments in registers (bf16x2, 64 regs) ----
    uint32_t wreg[2][8][4];
    #pragma unroll
    for (int mt = 0; mt < 2; mt++) {
        const float* rl = W_hh + (size_t)((2 * mt)     * 128 + u) * 128;
        const float* rh = W_hh + (size_t)((2 * mt + 1) * 128 + u) * 128;
        #pragma unroll
        for (int kt = 0; kt < 8; kt++) {
            int k0 = kt * 16 + tig * 2;
            wreg[mt][kt][0] = pk_bf16(__ldg(rl + k0),     __ldg(rl + k0 + 1));
            wreg[mt][kt][1] = pk_bf16(__ldg(rh + k0),     __ldg(rh + k0 + 1));
            wreg[mt][kt][2] = pk_bf16(__ldg(rl + k0 + 8), __ldg(rl + k0 + 9));
            wreg[mt][kt][3] = pk_bf16(__ldg(rh + k0 + 8), __ldg(rh + k0 + 9));
        }
    }

    __syncthreads();

    const uint32_t bfrag = hbase + (uint32_t)(gid * 32 + tig * 8);
    const int upair = u & ~1;
    const uint32_t wordoff = (uint32_t)((upair >> 4) * 1024 + ((upair >> 1) & 3) * 8
                                        + ((upair >> 3) & 1) * 4);
    const bool even = ((gid & 1) == 0);

    float cst[8];
    #pragma unroll
    for (int i = 0; i < 8; i++) cst[i] = 0.f;

    for (int t = 0; t < TT; t++) {
        const uint32_t rbo = (uint32_t)(t & 1) * 8192;
        const uint32_t wbo = (uint32_t)((t + 1) & 1) * 8192;

        float acc[2][4][4];
        #pragma unroll
        for (int mt = 0; mt < 2; mt++)
            #pragma unroll
            for (int nt = 0; nt < 4; nt++)
                #pragma unroll
                for (int r = 0; r < 4; r++) acc[mt][nt][r] = 0.f;

        // ---- MMA: D[512,32] += W @ h ----
        #pragma unroll
        for (int kt = 0; kt < 8; kt++) {
            uint32_t b0[4], b1[4];
            #pragma unroll
            for (int nt = 0; nt < 4; nt++)
                asm volatile("ld.shared.v2.b32 {%0,%1}, [%2];"
                             : "=r"(b0[nt]), "=r"(b1[nt])
                             : "r"(bfrag + rbo + (uint32_t)(kt * 1024 + nt * 256)));
            #pragma unroll
            for (int mt = 0; mt < 2; mt++)
                #pragma unroll
                for (int nt = 0; nt < 4; nt++)
                    MMA_BF16(acc[mt][nt], wreg[mt][kt], b0[nt], b1[nt]);
        }

        // ---- epilogue: gates + state update, publish h[next] ----
        {
            const float wi0 = wibs[u][0], wi1 = wibs[u][1];
            const float wi2 = wibs[u][2], wi3 = wibs[u][3];
            const float bs0 = wibs[u][4], bs1 = wibs[u][5];
            const float bs2 = wibs[u][6], bs3 = wibs[u][7];
            const uint32_t wL = hbase + wbo + wordoff;
            #pragma unroll
            for (int nt = 0; nt < 4; nt++) {
                #pragma unroll
                for (int e = 0; e < 2; e++) {
                    const int n = nt * 8 + tig * 2 + e;
                    const float xv = __bfloat162float(x_s[t * 32 + n]);
                    const float pi = acc[0][nt][e]     + fmaf(xv, wi0, bs0);
                    const float pf = acc[0][nt][2 + e] + fmaf(xv, wi1, bs1);
                    const float pg = acc[1][nt][e]     + fmaf(xv, wi2, bs2);
                    const float po = acc[1][nt][2 + e] + fmaf(xv, wi3, bs3);
                    const float gi = sig_ap(pi), gf = sig_ap(pf);
                    const float gg = tanh_ap(pg), go = sig_ap(po);
                    const float cn = fmaf(gf, cst[nt * 2 + e], gi * gg);
                    cst[nt * 2 + e] = cn;
                    const float hv = go * tanh_ap(cn);
                    const float hp = __shfl_xor_sync(0xffffffffu, hv, 4);
                    if (even) {
                        const uint32_t w = pk_bf16(hv, hp);
                        asm volatile("st.shared.b32 [%0], %1;"
                                     :: "r"(wL + (uint32_t)n * 32), "r"(w) : "memory");
                    }
                }
            }
        }
        __syncthreads();   // publish h[next]; also closes WAR on next write buf
    }

    // ---- fc head: final h (bf16) is in buffer 0 ----
    if (wid == 0) {
        const int n = lane;
        float s = fc_b[0];
        #pragma unroll 8
        for (int uu = 0; uu < 128; uu++) {
            const uint32_t addr = hbase + (uint32_t)((uu >> 4) * 1024 + n * 32
                               + ((uu >> 1) & 3) * 8 + ((uu >> 3) & 1) * 4 + (uu & 1) * 2);
            uint16_t hb;
            asm("ld.shared.u16 %0, [%1];" : "=h"(hb) : "r"(addr));
            const float hv = __uint_as_float(((uint32_t)hb) << 16);
            s = fmaf(hv, __ldg(fc_W + uu), s);
        }
        out[b0g + n] = s;
    }
}

extern "C" void kernel_launch(void* const* d_in, const int* in_sizes, int n_in,
                              void* d_out, int out_size)
{
    const float* x    = (const float*)d_in[0];
    const float* W_ih = (const float*)d_in[1];
    const float* W_hh = (const float*)d_in[2];
    const float* b_ih = (const float*)d_in[3];
    const float* b_hh = (const float*)d_in[4];
    const float* fc_W = (const float*)d_in[5];
    const float* fc_b = (const float*)d_in[6];

    const int B = in_sizes[0] / TT;    // 4096
    const int grid = B / 32;           // 128 CTAs, one wave

    lstm_mma<<<grid, NTHR>>>(x, W_ih, W_hh, b_ih, b_hh, fc_W, fc_b, (float*)d_out);
}

// round 10
// speedup vs baseline: 1.0909x; 1.0342x over previous
#include <cuda_runtime.h>
#include <cuda_bf16.h>
#include <cstdint>

// LSTM_WP — warp-specialized bf16 mma.sync with two independent batch streams.
// CTA: 640 threads = 16 MMA warps + 4 epi warps (one per SMSP). N=32 batches
// split into groups A (n 0-15) and B (n 16-31), independent recurrences.
// MMA warps: own all 512 gate rows (M=32/warp) as bf16x2 register frags;
//   per group-step compute D[512,16] = W @ h_g and store fp32 D to smem.
// Epi warps: read D, compute gates (MUFU), update c, write bf16 h to the
//   group's double-buffered smem tile; fp32 final h for the fc head.
// Sync: named barriers, producer bar.arrive + consumer bar.sync (count 640):
//   id 1/2 = h_A/h_B ready (epi -> MMA), id 3/4 = D_A/D_B ready (MMA -> epi).
// Steady state: epi(A,t) overlaps MMA(B,t) -> step-pair ~ tensor-bound.

#define TT 128
#define NTHR 640
#define NMMA_W 16

// dynamic smem layout (bytes)
#define OFF_D   0                 // 2 groups x 512 rows x 20 floats (pad) = 81920
#define D_GRP   40960
#define OFF_H   81920             // 2 groups x 2 bufs x 4096 B bf16 h
#define H_GRP   8192
#define OFF_X   98304             // x fp32 [t][n] stride 33 = 16896
#define OFF_HF  115200            // final h fp32 [u][n32] = 16384
#define SMEM_REQ 131584

__device__ __forceinline__ uint32_t smem_u32(const void* p) {
    uint32_t a;
    asm("{ .reg .u64 t; cvta.to.shared.u64 t, %1; cvt.u32.u64 %0, t; }" : "=r"(a) : "l"(p));
    return a;
}
__device__ __forceinline__ uint32_t pk_bf16(float lo, float hi) {
    uint32_t r; asm("cvt.rn.bf16x2.f32 %0, %1, %2;" : "=r"(r) : "f"(hi), "f"(lo)); return r;
}
__device__ __forceinline__ float tanh_ap(float x) {
    float y; asm("tanh.approx.f32 %0, %1;" : "=f"(y) : "f"(x)); return y;
}
__device__ __forceinline__ float sig_ap(float x) { return fmaf(tanh_ap(0.5f * x), 0.5f, 0.5f); }

#define BSYNC(id)   asm volatile("bar.sync %0, %1;"   :: "r"(id), "n"(NTHR) : "memory")
#define BARRIVE(id) asm volatile("bar.arrive %0, %1;" :: "r"(id), "n"(NTHR) : "memory")

#define MMA_BF16(d, a, b0, b1) \
    asm volatile("mma.sync.aligned.m16n8k16.row.col.f32.bf16.bf16.f32 " \
                 "{%0,%1,%2,%3}, {%4,%5,%6,%7}, {%8,%9}, {%0,%1,%2,%3};" \
                 : "+f"((d)[0]), "+f"((d)[1]), "+f"((d)[2]), "+f"((d)[3]) \
                 : "r"((a)[0]), "r"((a)[1]), "r"((a)[2]), "r"((a)[3]), \
                   "r"(b0), "r"(b1))

__global__ __launch_bounds__(NTHR, 1)
void lstm_ws(const float* __restrict__ x,
             const float* __restrict__ W_ih,
             const float* __restrict__ W_hh,
             const float* __restrict__ b_ih,
             const float* __restrict__ b_hh,
             const float* __restrict__ fc_W,
             const float* __restrict__ fc_b,
             float* __restrict__ out)
{
    extern __shared__ char sm[];
    const uint32_t sb = smem_u32(sm);
    const int tid = threadIdx.x, wid = tid >> 5, lane = tid & 31;
    const int gid = lane >> 2, tig = lane & 3;
    const int b0g = blockIdx.x * 32;

    // ---- stage x fp32 [t][n] (stride 33 to dodge bank conflicts); zero h ----
    float* xs = (float*)(sm + OFF_X);
    for (int i = tid; i < 32 * TT; i += NTHR) {
        int n = i >> 7, t = i & 127;
        xs[t * 33 + n] = x[(size_t)(b0g + n) * TT + t];
    }
    {
        uint32_t* hz = (uint32_t*)(sm + OFF_H);
        for (int i = tid; i < 4096; i += NTHR) hz[i] = 0u;   // both groups, both bufs
    }
    __syncthreads();

    if (wid < NMMA_W) {
        // ================= MMA warps =================
        const int u0 = wid * 8 + gid;                 // unit 0..127
        uint32_t wreg[2][8][4];
        #pragma unroll
        for (int mt = 0; mt < 2; mt++) {
            const float* rl = W_hh + (size_t)((2 * mt)     * 128 + u0) * 128;
            const float* rh = W_hh + (size_t)((2 * mt + 1) * 128 + u0) * 128;
            #pragma unroll
            for (int kt = 0; kt < 8; kt++) {
                int k0 = kt * 16 + tig * 2;
                wreg[mt][kt][0] = pk_bf16(__ldg(rl + k0),     __ldg(rl + k0 + 1));
                wreg[mt][kt][1] = pk_bf16(__ldg(rh + k0),     __ldg(rh + k0 + 1));
                wreg[mt][kt][2] = pk_bf16(__ldg(rl + k0 + 8), __ldg(rl + k0 + 9));
                wreg[mt][kt][3] = pk_bf16(__ldg(rh + k0 + 8), __ldg(rh + k0 + 9));
            }
        }

        for (int t = 0; t < TT; t++) {
            const uint32_t rb = (uint32_t)(t & 1) * 4096;
            #pragma unroll
            for (int g = 0; g < 2; g++) {
                BSYNC(1 + g);                          // h_g(t) ready
                float acc[2][2][4];
                #pragma unroll
                for (int mt = 0; mt < 2; mt++)
                    #pragma unroll
                    for (int nt = 0; nt < 2; nt++)
                        #pragma unroll
                        for (int r = 0; r < 4; r++) acc[mt][nt][r] = 0.f;

                const uint32_t hb = sb + OFF_H + (uint32_t)g * H_GRP + rb
                                  + (uint32_t)(gid * 32 + tig * 8);
                #pragma unroll
                for (int kt = 0; kt < 8; kt++) {
                    uint32_t b0[2], b1[2];
                    #pragma unroll
                    for (int nt = 0; nt < 2; nt++)
                        asm volatile("ld.shared.v2.b32 {%0,%1}, [%2];"
                                     : "=r"(b0[nt]), "=r"(b1[nt])
                                     : "r"(hb + (uint32_t)(kt * 512 + nt * 256)));
                    #pragma unroll
                    for (int mt = 0; mt < 2; mt++)
                        #pragma unroll
                        for (int nt = 0; nt < 2; nt++)
                            MMA_BF16(acc[mt][nt], wreg[mt][kt], b0[nt], b1[nt]);
                }
                // store D[row][n] fp32, row stride 20 floats
                const uint32_t db = sb + OFF_D + (uint32_t)g * D_GRP;
                #pragma unroll
                for (int mt = 0; mt < 2; mt++)
                    #pragma unroll
                    for (int nt = 0; nt < 2; nt++) {
                        const uint32_t rA = (uint32_t)((2 * mt) * 128 + u0);
                        const uint32_t n0 = (uint32_t)(nt * 8 + tig * 2);
                        asm volatile("st.shared.v2.f32 [%0], {%1,%2};"
                                     :: "r"(db + (rA * 20 + n0) * 4),
                                        "f"(acc[mt][nt][0]), "f"(acc[mt][nt][1]) : "memory");
                        asm volatile("st.shared.v2.f32 [%0], {%1,%2};"
                                     :: "r"(db + ((rA + 128) * 20 + n0) * 4),
                                        "f"(acc[mt][nt][2]), "f"(acc[mt][nt][3]) : "memory");
                    }
                BARRIVE(3 + g);                        // D_g(t) ready
            }
        }
    } else {
        // ================= epi warps =================
        const int u = (wid - NMMA_W) * 32 + lane;      // unit 0..127
        float wi[4], bsv[4];
        #pragma unroll
        for (int g4 = 0; g4 < 4; g4++) {
            int row = g4 * 128 + u;
            wi[g4]  = W_ih[row];
            bsv[g4] = b_ih[row] + b_hh[row];
        }
        float cst[2][16];
        #pragma unroll
        for (int g = 0; g < 2; g++)
            #pragma unroll
            for (int n = 0; n < 16; n++) cst[g][n] = 0.f;

        const uint32_t kt_off = (uint32_t)((u >> 4) * 512 + ((u & 7) >> 1) * 8
                                           + ((u >> 3) & 1) * 4);
        const bool even = ((u & 1) == 0);
        float* hf = (float*)(sm + OFF_HF);

        BARRIVE(1); BARRIVE(2);                        // initial h (zeros) published

        for (int t = 0; t < TT; t++) {
            const uint32_t wb = (uint32_t)((t + 1) & 1) * 4096;
            #pragma unroll
            for (int g = 0; g < 2; g++) {
                BSYNC(3 + g);                          // D_g(t) ready
                const uint32_t db = sb + OFF_D + (uint32_t)g * D_GRP;
                const uint32_t hw = sb + OFF_H + (uint32_t)g * H_GRP + wb + kt_off;
                #pragma unroll
                for (int q = 0; q < 4; q++) {
                    float d0[4], d1[4], d2[4], d3[4];
                    asm volatile("ld.shared.v4.f32 {%0,%1,%2,%3}, [%4];"
                                 : "=f"(d0[0]), "=f"(d0[1]), "=f"(d0[2]), "=f"(d0[3])
                                 : "r"(db + (uint32_t)((0 * 128 + u) * 20 + q * 4) * 4));
                    asm volatile("ld.shared.v4.f32 {%0,%1,%2,%3}, [%4];"
                                 : "=f"(d1[0]), "=f"(d1[1]), "=f"(d1[2]), "=f"(d1[3])
                                 : "r"(db + (uint32_t)((1 * 128 + u) * 20 + q * 4) * 4));
                    asm volatile("ld.shared.v4.f32 {%0,%1,%2,%3}, [%4];"
                                 : "=f"(d2[0]), "=f"(d2[1]), "=f"(d2[2]), "=f"(d2[3])
                                 : "r"(db + (uint32_t)((2 * 128 + u) * 20 + q * 4) * 4));
                    asm volatile("ld.shared.v4.f32 {%0,%1,%2,%3}, [%4];"
                                 : "=f"(d3[0]), "=f"(d3[1]), "=f"(d3[2]), "=f"(d3[3])
                                 : "r"(db + (uint32_t)((3 * 128 + u) * 20 + q * 4) * 4));
                    #pragma unroll
                    for (int j = 0; j < 4; j++) {
                        const int n = q * 4 + j;
                        const float xv = xs[t * 33 + g * 16 + n];
                        const float pi = d0[j] + fmaf(xv, wi[0], bsv[0]);
                        const float pf = d1[j] + fmaf(xv, wi[1], bsv[1]);
                        const float pg = d2[j] + fmaf(xv, wi[2], bsv[2]);
                        const float po = d3[j] + fmaf(xv, wi[3], bsv[3]);
                        const float gi = sig_ap(pi), gf = sig_ap(pf);
                        const float gg = tanh_ap(pg), go = sig_ap(po);
                        const float cn = fmaf(gf, cst[g][n], gi * gg);
                        cst[g][n] = cn;
                        const float hv = go * tanh_ap(cn);
                        const float hp = __shfl_xor_sync(0xffffffffu, hv, 1);
                        if (even) {
                            const uint32_t w = pk_bf16(hv, hp);
                            asm volatile("st.shared.b32 [%0], %1;"
                                         :: "r"(hw + (uint32_t)((n >> 3) * 256 + (n & 7) * 32)),
                                            "r"(w) : "memory");
                        }
                        if (t == TT - 1) hf[u * 32 + g * 16 + n] = hv;
                    }
                }
                BARRIVE(1 + g);                        // h_g(t+1) published
            }
        }
    }

    __syncthreads();
    // ---- fc head on fp32 final h ----
    if (wid == 0) {
        const int n = lane;
        const float* hf = (const float*)(sm + OFF_HF);
        float s = fc_b[0];
        #pragma unroll 8
        for (int u = 0; u < 128; u++)
            s = fmaf(hf[u * 32 + n], __ldg(fc_W + u), s);
        out[b0g + n] = s;
    }
}

extern "C" void kernel_launch(void* const* d_in, const int* in_sizes, int n_in,
                              void* d_out, int out_size)
{
    const float* x    = (const float*)d_in[0];
    const float* W_ih = (const float*)d_in[1];
    const float* W_hh = (const float*)d_in[2];
    const float* b_ih = (const float*)d_in[3];
    const float* b_hh = (const float*)d_in[4];
    const float* fc_W = (const float*)d_in[5];
    const float* fc_b = (const float*)d_in[6];

    const int B = in_sizes[0] / TT;    // 4096
    const int grid = B / 32;           // 128 CTAs, one wave

    cudaFuncSetAttribute(lstm_ws, cudaFuncAttributeMaxDynamicSharedMemorySize, SMEM_REQ);
    lstm_ws<<<grid, NTHR, SMEM_REQ>>>(x, W_ih, W_hh, b_ih, b_hh, fc_W, fc_b, (float*)d_out);
}

// round 11
// speedup vs baseline: 1.1375x; 1.0428x over previous
#include <cuda_runtime.h>
#include <cuda_bf16.h>
#include <cstdint>

// LSTM_WP — warp-specialized bf16 mma.sync, FOUR independent batch streams.
// CTA: 640 threads = 16 MMA warps + 4 epi warps. N=32 batches split into 4
// groups of 8 (independent recurrences) -> 4-deep producer/consumer pipeline:
// while epi handles group g, MMA warps run groups g+1..g+3. Named barriers:
//   id 1+g : h_g ready   (epi -> MMA; 512 bar.sync + 128 bar.arrive)
//   id 5+g : D_g ready   (MMA -> epi)
// MMA warps: all 512 gate rows as bf16x2 register frags (64 regs), per
// group-step D[512,8] = W @ h_g, stored fp32 to conflict-free padded smem.
// Epi warps: thread u owns unit u; per group 8 batches: gates (MUFU tanh),
// c update, bf16 h publish (double-buffered per group), fp32 final h.

#define TT 128
#define NTHR 640
#define NMMA_W 16

// dynamic smem (bytes)
#define OFF_D   0                  // 4 groups x 32 slots x 528 B = 67584
#define D_GRP   16896
#define D_SLOT  528                // (8 floats used, pad to 132 floats)
#define OFF_H   67584              // 4 groups x 2 bufs x 2048 B bf16 h
#define H_GRP   4096
#define OFF_X   83968              // x fp32 [t][n] stride 33 = 16896
#define OFF_HF  100864             // final h fp32 [u][n32] = 16384
#define SMEM_REQ 117248

__device__ __forceinline__ uint32_t smem_u32(const void* p) {
    uint32_t a;
    asm("{ .reg .u64 t; cvta.to.shared.u64 t, %1; cvt.u32.u64 %0, t; }" : "=r"(a) : "l"(p));
    return a;
}
__device__ __forceinline__ uint32_t pk_bf16(float lo, float hi) {
    uint32_t r; asm("cvt.rn.bf16x2.f32 %0, %1, %2;" : "=r"(r) : "f"(hi), "f"(lo)); return r;
}
__device__ __forceinline__ float tanh_ap(float x) {
    float y; asm("tanh.approx.f32 %0, %1;" : "=f"(y) : "f"(x)); return y;
}
__device__ __forceinline__ float sig_ap(float x) { return fmaf(tanh_ap(0.5f * x), 0.5f, 0.5f); }

#define BSYNC(id)   asm volatile("bar.sync %0, %1;"   :: "r"(id), "n"(NTHR) : "memory")
#define BARRIVE(id) asm volatile("bar.arrive %0, %1;" :: "r"(id), "n"(NTHR) : "memory")

#define MMA_BF16(d, a, b0, b1) \
    asm volatile("mma.sync.aligned.m16n8k16.row.col.f32.bf16.bf16.f32 " \
                 "{%0,%1,%2,%3}, {%4,%5,%6,%7}, {%8,%9}, {%0,%1,%2,%3};" \
                 : "+f"((d)[0]), "+f"((d)[1]), "+f"((d)[2]), "+f"((d)[3]) \
                 : "r"((a)[0]), "r"((a)[1]), "r"((a)[2]), "r"((a)[3]), \
                   "r"(b0), "r"(b1))

__global__ __launch_bounds__(NTHR, 1)
void lstm_ws4(const float* __restrict__ x,
              const float* __restrict__ W_ih,
              const float* __restrict__ W_hh,
              const float* __restrict__ b_ih,
              const float* __restrict__ b_hh,
              const float* __restrict__ fc_W,
              const float* __restrict__ fc_b,
              float* __restrict__ out)
{
    extern __shared__ char sm[];
    const uint32_t sb = smem_u32(sm);
    const int tid = threadIdx.x, wid = tid >> 5, lane = tid & 31;
    const int gid = lane >> 2, tig = lane & 3;
    const int b0g = blockIdx.x * 32;

    // ---- stage x fp32 [t][n] stride 33; zero all h buffers ----
    float* xs = (float*)(sm + OFF_X);
    for (int i = tid; i < 32 * TT; i += NTHR) {
        int n = i >> 7, t = i & 127;
        xs[t * 33 + n] = x[(size_t)(b0g + n) * TT + t];
    }
    {
        uint32_t* hz = (uint32_t*)(sm + OFF_H);
        for (int i = tid; i < 4096; i += NTHR) hz[i] = 0u;
    }
    __syncthreads();

    if (wid < NMMA_W) {
        // ================= MMA warps =================
        const int u0 = wid * 8 + gid;                 // unit 0..127
        uint32_t wreg[2][8][4];
        #pragma unroll
        for (int mt = 0; mt < 2; mt++) {
            const float* rl = W_hh + (size_t)((2 * mt)     * 128 + u0) * 128;
            const float* rh = W_hh + (size_t)((2 * mt + 1) * 128 + u0) * 128;
            #pragma unroll
            for (int kt = 0; kt < 8; kt++) {
                int k0 = kt * 16 + tig * 2;
                wreg[mt][kt][0] = pk_bf16(__ldg(rl + k0),     __ldg(rl + k0 + 1));
                wreg[mt][kt][1] = pk_bf16(__ldg(rh + k0),     __ldg(rh + k0 + 1));
                wreg[mt][kt][2] = pk_bf16(__ldg(rl + k0 + 8), __ldg(rl + k0 + 9));
                wreg[mt][kt][3] = pk_bf16(__ldg(rh + k0 + 8), __ldg(rh + k0 + 9));
            }
        }

        // per-thread store addrs: c01 -> (g4=2mt, n=2tig+e, u0); c23 -> g4+1
        for (int t = 0; t < TT; t++) {
            const uint32_t rb = (uint32_t)(t & 1) * 2048;
            #pragma unroll
            for (int g = 0; g < 4; g++) {
                BSYNC(1 + g);                          // h_g(t) ready
                float acc[2][4];
                #pragma unroll
                for (int mt = 0; mt < 2; mt++)
                    #pragma unroll
                    for (int r = 0; r < 4; r++) acc[mt][r] = 0.f;

                const uint32_t hb = sb + OFF_H + (uint32_t)g * H_GRP + rb
                                  + (uint32_t)(gid * 32 + tig * 8);
                #pragma unroll
                for (int kt = 0; kt < 8; kt++) {
                    uint32_t b0, b1;
                    asm volatile("ld.shared.v2.b32 {%0,%1}, [%2];"
                                 : "=r"(b0), "=r"(b1)
                                 : "r"(hb + (uint32_t)(kt * 256)));
                    MMA_BF16(acc[0], wreg[0][kt], b0, b1);
                    MMA_BF16(acc[1], wreg[1][kt], b0, b1);
                }
                // store D: slot (g4*8+n), stride D_SLOT bytes, + u*4
                const uint32_t db = sb + OFF_D + (uint32_t)g * D_GRP + (uint32_t)(u0 * 4);
                #pragma unroll
                for (int mt = 0; mt < 2; mt++) {
                    #pragma unroll
                    for (int e = 0; e < 2; e++) {
                        const uint32_t n = (uint32_t)(tig * 2 + e);
                        asm volatile("st.shared.f32 [%0], %1;"
                                     :: "r"(db + ((uint32_t)(2 * mt) * 8 + n) * D_SLOT),
                                        "f"(acc[mt][e]) : "memory");
                        asm volatile("st.shared.f32 [%0], %1;"
                                     :: "r"(db + ((uint32_t)(2 * mt + 1) * 8 + n) * D_SLOT),
                                        "f"(acc[mt][2 + e]) : "memory");
                    }
                }
                BARRIVE(5 + g);                        // D_g(t) ready
            }
        }
    } else {
        // ================= epi warps =================
        const int u = (wid - NMMA_W) * 32 + lane;      // unit 0..127
        float wi[4], bsv[4];
        #pragma unroll
        for (int g4 = 0; g4 < 4; g4++) {
            int row = g4 * 128 + u;
            wi[g4]  = W_ih[row];
            bsv[g4] = b_ih[row] + b_hh[row];
        }
        float cst[4][8];
        #pragma unroll
        for (int g = 0; g < 4; g++)
            #pragma unroll
            for (int n = 0; n < 8; n++) cst[g][n] = 0.f;

        const uint32_t kt_off = (uint32_t)((u >> 4) * 256 + ((u & 7) >> 1) * 8
                                           + ((u >> 3) & 1) * 4);
        const bool even = ((u & 1) == 0);
        float* hf = (float*)(sm + OFF_HF);

        BARRIVE(1); BARRIVE(2); BARRIVE(3); BARRIVE(4);   // initial zeros

        for (int t = 0; t < TT; t++) {
            const uint32_t wb = (uint32_t)((t + 1) & 1) * 2048;
            #pragma unroll
            for (int g = 0; g < 4; g++) {
                BSYNC(5 + g);                          // D_g(t) ready
                const uint32_t db = sb + OFF_D + (uint32_t)g * D_GRP + (uint32_t)(u * 4);
                const uint32_t hw = sb + OFF_H + (uint32_t)g * H_GRP + wb + kt_off;
                float d0[8], d1[8], d2[8], d3[8];
                #pragma unroll
                for (int n = 0; n < 8; n++) {
                    asm volatile("ld.shared.f32 %0, [%1];" : "=f"(d0[n])
                                 : "r"(db + (uint32_t)(0 * 8 + n) * D_SLOT));
                    asm volatile("ld.shared.f32 %0, [%1];" : "=f"(d1[n])
                                 : "r"(db + (uint32_t)(1 * 8 + n) * D_SLOT));
                    asm volatile("ld.shared.f32 %0, [%1];" : "=f"(d2[n])
                                 : "r"(db + (uint32_t)(2 * 8 + n) * D_SLOT));
                    asm volatile("ld.shared.f32 %0, [%1];" : "=f"(d3[n])
                                 : "r"(db + (uint32_t)(3 * 8 + n) * D_SLOT));
                }
                #pragma unroll
                for (int n = 0; n < 8; n++) {
                    const float xv = xs[t * 33 + g * 8 + n];
                    const float pi = d0[n] + fmaf(xv, wi[0], bsv[0]);
                    const float pf = d1[n] + fmaf(xv, wi[1], bsv[1]);
                    const float pg = d2[n] + fmaf(xv, wi[2], bsv[2]);
                    const float po = d3[n] + fmaf(xv, wi[3], bsv[3]);
                    const float gi = sig_ap(pi), gf = sig_ap(pf);
                    const float gg = tanh_ap(pg), go = sig_ap(po);
                    const float cn = fmaf(gf, cst[g][n], gi * gg);
                    cst[g][n] = cn;
                    const float hv = go * tanh_ap(cn);
                    const float hp = __shfl_xor_sync(0xffffffffu, hv, 1);
                    if (even) {
                        const uint32_t w = pk_bf16(hv, hp);
                        asm volatile("st.shared.b32 [%0], %1;"
                                     :: "r"(hw + (uint32_t)n * 32), "r"(w) : "memory");
                    }
                    if (t == TT - 1) hf[u * 32 + g * 8 + n] = hv;
                }
                BARRIVE(1 + g);                        // h_g(t+1) published
            }
        }
    }

    __syncthreads();
    // ---- fc head on fp32 final h ----
    if (wid == 0) {
        const int n = lane;
        const float* hf = (const float*)(sm + OFF_HF);
        float s = fc_b[0];
        #pragma unroll 8
        for (int u = 0; u < 128; u++)
            s = fmaf(hf[u * 32 + n], __ldg(fc_W + u), s);
        out[b0g + n] = s;
    }
}

extern "C" void kernel_launch(void* const* d_in, const int* in_sizes, int n_in,
                              void* d_out, int out_size)
{
    const float* x    = (const float*)d_in[0];
    const float* W_ih = (const float*)d_in[1];
    const float* W_hh = (const float*)d_in[2];
    const float* b_ih = (const float*)d_in[3];
    const float* b_hh = (const float*)d_in[4];
    const float* fc_W = (const float*)d_in[5];
    const float* fc_b = (const float*)d_in[6];

    const int B = in_sizes[0] / TT;    // 4096
    const int grid = B / 32;           // 128 CTAs, one wave

    cudaFuncSetAttribute(lstm_ws4, cudaFuncAttributeMaxDynamicSharedMemorySize, SMEM_REQ);
    lstm_ws4<<<grid, NTHR, SMEM_REQ>>>(x, W_ih, W_hh, b_ih, b_hh, fc_W, fc_b, (float*)d_out);
}

// round 13
// speedup vs baseline: 1.6139x; 1.4188x over previous
#include <cuda_runtime.h>
#include <cuda_bf16.h>
#include <cstdint>

// LSTM_WP — fused bf16 mma.sync, 4 rotated batch-groups, mbarrier phases.
// Single CTA, 512 threads (16 warps). Warp w owns units u0 = w*8+gid (all 4
// gates, 32 rows) as bf16x2 register frags. N=32 batches in 4 groups of 8;
// warp processes groups in rotated order g=(wid+j)&3 so warps drift and
// tensor/MUFU/LSU pipes overlap. D never goes to smem: each warp's acc holds
// all 4 gates for its own units -> epilogue is warp-local (shfl pair-pack).
// Per group: phase-tracked shared::cta mbarrier (16 arrivals, parity=t&1).
// h bf16 double-buffered per group; x fp32; final h fp32 for exact fc head.

#define TT 128
#define NTHR 512

// dynamic smem (bytes)
#define OFF_H   0            // 4 groups x 2 bufs x 2048
#define H_GRP   4096
#define OFF_X   16384        // 128 t x 33 floats = 16896
#define OFF_HF  33280        // 128 u x 32 n x 4 = 16384
#define OFF_BAR 49664        // 4 mbarriers
#define SMEM_REQ 49728

__device__ __forceinline__ uint32_t smem_u32(const void* p) {
    uint32_t a;
    asm("{ .reg .u64 t; cvta.to.shared.u64 t, %1; cvt.u32.u64 %0, t; }" : "=r"(a) : "l"(p));
    return a;
}
__device__ __forceinline__ uint32_t pk_bf16(float lo, float hi) {
    uint32_t r; asm("cvt.rn.bf16x2.f32 %0, %1, %2;" : "=r"(r) : "f"(hi), "f"(lo)); return r;
}
__device__ __forceinline__ float tanh_ap(float x) {
    float y; asm("tanh.approx.f32 %0, %1;" : "=f"(y) : "f"(x)); return y;
}
__device__ __forceinline__ float sig_ap(float x) { return fmaf(tanh_ap(0.5f * x), 0.5f, 0.5f); }

#define MBAR_INIT(a, n) \
    asm volatile("mbarrier.init.shared.b64 [%0], %1;" :: "r"(a), "r"((uint32_t)(n)) : "memory")
#define MBAR_ARRIVE(a) \
    asm volatile("mbarrier.arrive.shared.b64 _, [%0];" :: "r"(a) : "memory")

__device__ __forceinline__ void mbar_wait(uint32_t a, uint32_t par) {
    uint32_t done;
    do {
        asm volatile("{ .reg .pred p;"
                     " mbarrier.try_wait.parity.shared.b64 p, [%1], %2, 0x989680;"
                     " selp.b32 %0,1,0,p; }"
                     : "=r"(done) : "r"(a), "r"(par) : "memory");
    } while (!done);
}

#define MMA_BF16(d, a, b0, b1) \
    asm volatile("mma.sync.aligned.m16n8k16.row.col.f32.bf16.bf16.f32 " \
                 "{%0,%1,%2,%3}, {%4,%5,%6,%7}, {%8,%9}, {%0,%1,%2,%3};" \
                 : "+f"((d)[0]), "+f"((d)[1]), "+f"((d)[2]), "+f"((d)[3]) \
                 : "r"((a)[0]), "r"((a)[1]), "r"((a)[2]), "r"((a)[3]), \
                   "r"(b0), "r"(b1))

__global__ __launch_bounds__(NTHR, 1)
void lstm_rot(const float* __restrict__ x,
              const float* __restrict__ W_ih,
              const float* __restrict__ W_hh,
              const float* __restrict__ b_ih,
              const float* __restrict__ b_hh,
              const float* __restrict__ fc_W,
              const float* __restrict__ fc_b,
              float* __restrict__ out)
{
    extern __shared__ char sm[];
    const uint32_t sb = smem_u32(sm);
    const int tid = threadIdx.x, wid = tid >> 5, lane = tid & 31;
    const int gid = lane >> 2, tig = lane & 3;
    const int b0g = blockIdx.x * 32;

    // ---- init: mbarriers, x fp32 [t][33], zero h (both bufs, all groups) ----
    if (tid == 0) {
        #pragma unroll
        for (int g = 0; g < 4; g++) MBAR_INIT(sb + OFF_BAR + g * 8, 16);
    }
    float* xs = (float*)(sm + OFF_X);
    for (int i = tid; i < 32 * TT; i += NTHR) {
        int n = i >> 7, t = i & 127;
        xs[t * 33 + n] = x[(size_t)(b0g + n) * TT + t];
    }
    {
        uint32_t* hz = (uint32_t*)(sm + OFF_H);
        for (int i = tid; i < 4096; i += NTHR) hz[i] = 0u;
    }

    // ---- W fragments in registers (bf16x2, 64 regs) ----
    const int u0 = wid * 8 + gid;                 // unit 0..127
    uint32_t wreg[2][8][4];
    #pragma unroll
    for (int mt = 0; mt < 2; mt++) {
        const float* rl = W_hh + (size_t)((2 * mt)     * 128 + u0) * 128;
        const float* rh = W_hh + (size_t)((2 * mt + 1) * 128 + u0) * 128;
        #pragma unroll
        for (int kt = 0; kt < 8; kt++) {
            int k0 = kt * 16 + tig * 2;
            wreg[mt][kt][0] = pk_bf16(__ldg(rl + k0),     __ldg(rl + k0 + 1));
            wreg[mt][kt][1] = pk_bf16(__ldg(rh + k0),     __ldg(rh + k0 + 1));
            wreg[mt][kt][2] = pk_bf16(__ldg(rl + k0 + 8), __ldg(rl + k0 + 9));
            wreg[mt][kt][3] = pk_bf16(__ldg(rh + k0 + 8), __ldg(rh + k0 + 9));
        }
    }
    float wi[4], bsv[4];
    #pragma unroll
    for (int g4 = 0; g4 < 4; g4++) {
        int row = g4 * 128 + u0;
        wi[g4]  = W_ih[row];
        bsv[g4] = b_ih[row] + b_hh[row];
    }

    const uint32_t lane_rd = (uint32_t)(gid * 32 + tig * 8);          // B-frag lane off
    const int upair = u0 & ~1;
    const uint32_t wordoff = (uint32_t)((upair >> 4) * 256 + ((upair >> 1) & 3) * 8
                                        + ((upair >> 3) & 1) * 4);
    const bool even = ((gid & 1) == 0);
    float* hf = (float*)(sm + OFF_HF);

    float cst[4][2];
    #pragma unroll
    for (int g = 0; g < 4; g++) { cst[g][0] = 0.f; cst[g][1] = 0.f; }

    __syncthreads();   // x + zero-h + mbar init visible

    for (int t = 0; t < TT; t++) {
        const uint32_t rbo = (uint32_t)(t & 1) * 2048;
        const uint32_t wbo = (uint32_t)((t + 1) & 1) * 2048;
        #pragma unroll
        for (int j = 0; j < 4; j++) {
            const int g = (wid + j) & 3;
            const uint32_t gb = sb + OFF_H + (uint32_t)g * H_GRP;
            // wait: all 16 warps published h_g(t) (phase t-1); t=0 reads zeros
            if (t > 0) mbar_wait(sb + OFF_BAR + (uint32_t)g * 8, (uint32_t)((t - 1) & 1));

            // ---- MMA: 2 mt x (two 4-deep k chains) ----
            float acc[2][2][4];
            #pragma unroll
            for (int mt = 0; mt < 2; mt++)
                #pragma unroll
                for (int kh = 0; kh < 2; kh++)
                    #pragma unroll
                    for (int r = 0; r < 4; r++) acc[mt][kh][r] = 0.f;
            const uint32_t hb = gb + rbo + lane_rd;
            #pragma unroll
            for (int kt = 0; kt < 8; kt++) {
                uint32_t b0, b1;
                asm volatile("ld.shared.v2.b32 {%0,%1}, [%2];"
                             : "=r"(b0), "=r"(b1) : "r"(hb + (uint32_t)(kt * 256)));
                MMA_BF16(acc[0][kt >> 2], wreg[0][kt], b0, b1);
                MMA_BF16(acc[1][kt >> 2], wreg[1][kt], b0, b1);
            }

            // ---- epilogue (warp-local: acc holds all 4 gates of unit u0) ----
            const uint32_t wL = gb + wbo + wordoff;
            #pragma unroll
            for (int e = 0; e < 2; e++) {
                const int n = tig * 2 + e;
                const float xv = xs[t * 33 + g * 8 + n];
                const float pi = (acc[0][0][e]     + acc[0][1][e])     + fmaf(xv, wi[0], bsv[0]);
                const float pf = (acc[0][0][2 + e] + acc[0][1][2 + e]) + fmaf(xv, wi[1], bsv[1]);
                const float pg = (acc[1][0][e]     + acc[1][1][e])     + fmaf(xv, wi[2], bsv[2]);
                const float po = (acc[1][0][2 + e] + acc[1][1][2 + e]) + fmaf(xv, wi[3], bsv[3]);
                const float gi = sig_ap(pi), gf = sig_ap(pf);
                const float gg = tanh_ap(pg), go = sig_ap(po);
                const float cn = fmaf(gf, cst[g][e], gi * gg);
                cst[g][e] = cn;
                const float hv = go * tanh_ap(cn);
                const float hp = __shfl_xor_sync(0xffffffffu, hv, 4);
                if (even) {
                    const uint32_t w = pk_bf16(hv, hp);
                    asm volatile("st.shared.b32 [%0], %1;"
                                 :: "r"(wL + (uint32_t)n * 32), "r"(w) : "memory");
                }
                if (t == TT - 1) hf[u0 * 32 + g * 8 + n] = hv;
            }
            __syncwarp();
            if (lane == 0) MBAR_ARRIVE(sb + OFF_BAR + (uint32_t)g * 8);
        }
    }

    __syncthreads();   // hf complete
    // ---- fc head on fp32 final h ----
    if (wid == 0) {
        const int n = lane;
        float s = fc_b[0];
        #pragma unroll 8
        for (int u = 0; u < 128; u++)
            s = fmaf(hf[u * 32 + n], __ldg(fc_W + u), s);
        out[b0g + n] = s;
    }
}

extern "C" void kernel_launch(void* const* d_in, const int* in_sizes, int n_in,
                              void* d_out, int out_size)
{
    const float* x    = (const float*)d_in[0];
    const float* W_ih = (const float*)d_in[1];
    const float* W_hh = (const float*)d_in[2];
    const float* b_ih = (const float*)d_in[3];
    const float* b_hh = (const float*)d_in[4];
    const float* fc_W = (const float*)d_in[5];
    const float* fc_b = (const float*)d_in[6];

    const int B = in_sizes[0] / TT;    // 4096
    const int grid = B / 32;           // 128 CTAs, one wave

    cudaFuncSetAttribute(lstm_rot, cudaFuncAttributeMaxDynamicSharedMemorySize, SMEM_REQ);
    lstm_rot<<<grid, NTHR, SMEM_REQ>>>(x, W_ih, W_hh, b_ih, b_hh, fc_W, fc_b, (float*)d_out);
}